// round 4
// baseline (speedup 1.0000x reference)
#include <cuda_runtime.h>
#include <cuda_bf16.h>
#include <mma.h>
#include <cstdint>

using namespace nvcuda;

#define N_NODES 50000
#define N_EDGES 800000
#define DIM 128
#define NLAYERS 3
#define NBLK_NODE 196   // ceil(50000/256)

// ---------------------------------------------------------------------------
// Scratch (no allocations allowed -> __device__ globals)
// ---------------------------------------------------------------------------
__device__ float g_hA[N_NODES * DIM];
__device__ float g_hB[N_NODES * DIM];
__device__ int   g_deg[N_NODES];
__device__ int   g_off[N_NODES + 1];
__device__ int   g_cur[N_NODES];
__device__ int   g_srcs[N_EDGES];
__device__ int   g_bsum[256];
__device__ int   g_bbase[256];

// ---------------------------------------------------------------------------
// bf16 hi/lo split of a pair of floats, packed as bf16x2 words
// ---------------------------------------------------------------------------
__device__ __forceinline__ void split2(float a0, float a1, uint32_t& hi, uint32_t& lo) {
    __nv_bfloat16 h0 = __float2bfloat16(a0);
    __nv_bfloat16 h1 = __float2bfloat16(a1);
    float r0 = a0 - __bfloat162float(h0);
    float r1 = a1 - __bfloat162float(h1);
    __nv_bfloat16 l0 = __float2bfloat16(r0);
    __nv_bfloat16 l1 = __float2bfloat16(r1);
    hi = (uint32_t)__bfloat16_as_ushort(h0) | ((uint32_t)__bfloat16_as_ushort(h1) << 16);
    lo = (uint32_t)__bfloat16_as_ushort(l0) | ((uint32_t)__bfloat16_as_ushort(l1) << 16);
}

// Staging buffer offsets (bytes) within the staging region
#define A_HI 0
#define A_LO 10240
#define W_HI 20480
#define W_LO 29184
#define STAGE_BYTES 37888   // also reused as 8 warps x 16x68 fp32 epilogue scratch

// Dynamic smem layout of fused kernel: [0,67584) agg tile fp32 (128 x 132), then staging
#define AGG_LDM 132
#define AGG_BYTES 67584
#define FUSED_SMEM (AGG_BYTES + STAGE_BYTES)   // 105472

// ---------------------------------------------------------------------------
// Shared GEMM core pieces as macros would be unwieldy; we write two kernels.
// Warp layout (both): 8 warps as 4(m) x 2(n); warp tile 32x64 of a 128x128 CTA tile.
// ---------------------------------------------------------------------------

// ======================= in_fc kernel: out = x @ W + b =====================
__global__ __launch_bounds__(256) void gemm_infc_kernel(
    const float* __restrict__ A1, const float* __restrict__ W1,
    const float* __restrict__ bias, float* __restrict__ out)
{
    __shared__ __align__(16) char smem_raw[STAGE_BYTES];

    const int tid  = threadIdx.x;
    const int wid  = tid >> 5;
    const int lane = tid & 31;
    const int wm   = wid & 3;
    const int wn   = wid >> 2;
    const int row0 = blockIdx.x * 128;

    wmma::fragment<wmma::accumulator, 16, 16, 16, float> acc[2][4];
#pragma unroll
    for (int mi = 0; mi < 2; mi++)
#pragma unroll
        for (int ni = 0; ni < 4; ni++)
            wmma::fill_fragment(acc[mi][ni], 0.0f);

    for (int kc = 0; kc < 4; kc++) {
        const int k0 = kc * 32;
        __syncthreads();
#pragma unroll
        for (int t = 0; t < 4; t++) {
            int q  = tid + t * 256;
            int r  = q >> 3;
            int c4 = q & 7;
            int gr = row0 + r;
            float4 v = make_float4(0.f, 0.f, 0.f, 0.f);
            if (gr < N_NODES)
                v = *reinterpret_cast<const float4*>(A1 + (size_t)gr * DIM + k0 + c4 * 4);
            uint32_t h0, l0, h1, l1;
            split2(v.x, v.y, h0, l0);
            split2(v.z, v.w, h1, l1);
            uint32_t boff = (uint32_t)r * 80u + (uint32_t)c4 * 8u;
            *reinterpret_cast<uint2*>(smem_raw + A_HI + boff) = make_uint2(h0, h1);
            *reinterpret_cast<uint2*>(smem_raw + A_LO + boff) = make_uint2(l0, l1);
        }
#pragma unroll
        for (int t = 0; t < 4; t++) {
            int q  = tid + t * 256;
            int kk = q >> 5;
            int c4 = q & 31;
            float4 v = *reinterpret_cast<const float4*>(W1 + (size_t)(k0 + kk) * DIM + c4 * 4);
            uint32_t h0, l0, h1, l1;
            split2(v.x, v.y, h0, l0);
            split2(v.z, v.w, h1, l1);
            uint32_t boff = (uint32_t)kk * 272u + (uint32_t)c4 * 8u;
            *reinterpret_cast<uint2*>(smem_raw + W_HI + boff) = make_uint2(h0, h1);
            *reinterpret_cast<uint2*>(smem_raw + W_LO + boff) = make_uint2(l0, l1);
        }
        __syncthreads();

#pragma unroll
        for (int ks = 0; ks < 2; ks++) {
            wmma::fragment<wmma::matrix_a, 16, 16, 16, __nv_bfloat16, wmma::row_major> ah[2], al[2];
#pragma unroll
            for (int mi = 0; mi < 2; mi++) {
                const __nv_bfloat16* pa_hi = reinterpret_cast<const __nv_bfloat16*>(smem_raw + A_HI)
                                           + (wm * 32 + mi * 16) * 40 + ks * 16;
                const __nv_bfloat16* pa_lo = reinterpret_cast<const __nv_bfloat16*>(smem_raw + A_LO)
                                           + (wm * 32 + mi * 16) * 40 + ks * 16;
                wmma::load_matrix_sync(ah[mi], pa_hi, 40);
                wmma::load_matrix_sync(al[mi], pa_lo, 40);
            }
#pragma unroll
            for (int ni = 0; ni < 4; ni++) {
                wmma::fragment<wmma::matrix_b, 16, 16, 16, __nv_bfloat16, wmma::row_major> bh, bl;
                const __nv_bfloat16* pb_hi = reinterpret_cast<const __nv_bfloat16*>(smem_raw + W_HI)
                                           + (ks * 16) * 136 + wn * 64 + ni * 16;
                const __nv_bfloat16* pb_lo = reinterpret_cast<const __nv_bfloat16*>(smem_raw + W_LO)
                                           + (ks * 16) * 136 + wn * 64 + ni * 16;
                wmma::load_matrix_sync(bh, pb_hi, 136);
                wmma::load_matrix_sync(bl, pb_lo, 136);
#pragma unroll
                for (int mi = 0; mi < 2; mi++) {
                    wmma::mma_sync(acc[mi][ni], ah[mi], bh, acc[mi][ni]);
                    wmma::mma_sync(acc[mi][ni], ah[mi], bl, acc[mi][ni]);
                    wmma::mma_sync(acc[mi][ni], al[mi], bh, acc[mi][ni]);
                }
            }
        }
    }

    __syncthreads();
    float* sc = reinterpret_cast<float*>(smem_raw) + wid * (16 * 68);
    const int col0 = wn * 64;
    const int rl   = lane >> 1;
    const int half = lane & 1;
#pragma unroll
    for (int mi = 0; mi < 2; mi++) {
#pragma unroll
        for (int ni = 0; ni < 4; ni++)
            wmma::store_matrix_sync(sc + ni * 16, acc[mi][ni], 68, wmma::mem_row_major);
        __syncwarp();
        int grow = row0 + wm * 32 + mi * 16 + rl;
        if (grow < N_NODES) {
#pragma unroll
            for (int j = 0; j < 8; j++) {
                int c = half * 32 + j * 4;
                float4 v  = *reinterpret_cast<const float4*>(sc + rl * 68 + c);
                float4 b4 = *reinterpret_cast<const float4*>(bias + col0 + c);
                v.x += b4.x; v.y += b4.y; v.z += b4.z; v.w += b4.w;
                *reinterpret_cast<float4*>(out + (size_t)grow * DIM + col0 + c) = v;
            }
        }
        __syncwarp();
    }
}

// ============ fused layer kernel: gather + GEMM + epilogue =================
//   agg = segment_sum(hin[src], dst)  (rows of this CTA only, into smem)
//   out = relu([agg|hin] @ [W1;W2] + bias) + hin
__global__ __launch_bounds__(256) void fused_layer_kernel(
    const float* __restrict__ hin, const float* __restrict__ W1,
    const float* __restrict__ W2, const float* __restrict__ bias,
    float* __restrict__ out)
{
    extern __shared__ __align__(16) char dsm[];
    float* sAgg = reinterpret_cast<float*>(dsm);        // 128 x AGG_LDM fp32
    char*  stage = dsm + AGG_BYTES;

    const int tid  = threadIdx.x;
    const int wid  = tid >> 5;
    const int lane = tid & 31;
    const int wm   = wid & 3;
    const int wn   = wid >> 2;
    const int row0 = blockIdx.x * 128;

    // ---------------- Phase 1: gather neighbor sums for 128 nodes ----------
    const float4* __restrict__ h4 = reinterpret_cast<const float4*>(hin);
#pragma unroll 1
    for (int t = 0; t < 16; t++) {
        const int n_local = wid * 16 + t;
        const int gn = row0 + n_local;
        float4 acc = make_float4(0.f, 0.f, 0.f, 0.f);
        if (gn < N_NODES) {
            int s = g_off[gn];
            int e = g_off[gn + 1];
            int i = s;
            while (i < e) {
                int cnt = min(e - i, 32);
                int idx = (lane < cnt) ? g_srcs[i + lane] : 0;
                int j = 0;
                for (; j + 4 <= cnt; j += 4) {
                    int s0 = __shfl_sync(0xFFFFFFFFu, idx, j);
                    int s1 = __shfl_sync(0xFFFFFFFFu, idx, j + 1);
                    int s2 = __shfl_sync(0xFFFFFFFFu, idx, j + 2);
                    int s3 = __shfl_sync(0xFFFFFFFFu, idx, j + 3);
                    float4 v0 = h4[(size_t)s0 * 32 + lane];
                    float4 v1 = h4[(size_t)s1 * 32 + lane];
                    float4 v2 = h4[(size_t)s2 * 32 + lane];
                    float4 v3 = h4[(size_t)s3 * 32 + lane];
                    acc.x += (v0.x + v1.x) + (v2.x + v3.x);
                    acc.y += (v0.y + v1.y) + (v2.y + v3.y);
                    acc.z += (v0.z + v1.z) + (v2.z + v3.z);
                    acc.w += (v0.w + v1.w) + (v2.w + v3.w);
                }
                for (; j < cnt; j++) {
                    int s0 = __shfl_sync(0xFFFFFFFFu, idx, j);
                    float4 v0 = h4[(size_t)s0 * 32 + lane];
                    acc.x += v0.x; acc.y += v0.y; acc.z += v0.z; acc.w += v0.w;
                }
                i += cnt;
            }
        }
        *reinterpret_cast<float4*>(sAgg + n_local * AGG_LDM + lane * 4) = acc;
    }
    __syncthreads();

    // ---------------- Phase 2: GEMM, K = 256 (agg cols 0-127, hin 128-255) -
    wmma::fragment<wmma::accumulator, 16, 16, 16, float> acc[2][4];
#pragma unroll
    for (int mi = 0; mi < 2; mi++)
#pragma unroll
        for (int ni = 0; ni < 4; ni++)
            wmma::fill_fragment(acc[mi][ni], 0.0f);

    for (int kc = 0; kc < 8; kc++) {
        const int k0 = kc * 32;
        __syncthreads();
#pragma unroll
        for (int t = 0; t < 4; t++) {
            int q  = tid + t * 256;
            int r  = q >> 3;
            int c4 = q & 7;
            int col = k0 + c4 * 4;
            int gr  = row0 + r;
            float4 v;
            if (col < 128) {
                v = *reinterpret_cast<const float4*>(sAgg + r * AGG_LDM + col);
            } else {
                v = make_float4(0.f, 0.f, 0.f, 0.f);
                if (gr < N_NODES)
                    v = *reinterpret_cast<const float4*>(hin + (size_t)gr * DIM + (col - 128));
            }
            uint32_t h0, l0, h1, l1;
            split2(v.x, v.y, h0, l0);
            split2(v.z, v.w, h1, l1);
            uint32_t boff = (uint32_t)r * 80u + (uint32_t)c4 * 8u;
            *reinterpret_cast<uint2*>(stage + A_HI + boff) = make_uint2(h0, h1);
            *reinterpret_cast<uint2*>(stage + A_LO + boff) = make_uint2(l0, l1);
        }
#pragma unroll
        for (int t = 0; t < 4; t++) {
            int q  = tid + t * 256;
            int kk = q >> 5;
            int c4 = q & 31;
            int krow = k0 + kk;
            const float* base = (krow < 128) ? W1 : W2;
            int kr = (krow < 128) ? krow : krow - 128;
            float4 v = *reinterpret_cast<const float4*>(base + (size_t)kr * DIM + c4 * 4);
            uint32_t h0, l0, h1, l1;
            split2(v.x, v.y, h0, l0);
            split2(v.z, v.w, h1, l1);
            uint32_t boff = (uint32_t)kk * 272u + (uint32_t)c4 * 8u;
            *reinterpret_cast<uint2*>(stage + W_HI + boff) = make_uint2(h0, h1);
            *reinterpret_cast<uint2*>(stage + W_LO + boff) = make_uint2(l0, l1);
        }
        __syncthreads();

#pragma unroll
        for (int ks = 0; ks < 2; ks++) {
            wmma::fragment<wmma::matrix_a, 16, 16, 16, __nv_bfloat16, wmma::row_major> ah[2], al[2];
#pragma unroll
            for (int mi = 0; mi < 2; mi++) {
                const __nv_bfloat16* pa_hi = reinterpret_cast<const __nv_bfloat16*>(stage + A_HI)
                                           + (wm * 32 + mi * 16) * 40 + ks * 16;
                const __nv_bfloat16* pa_lo = reinterpret_cast<const __nv_bfloat16*>(stage + A_LO)
                                           + (wm * 32 + mi * 16) * 40 + ks * 16;
                wmma::load_matrix_sync(ah[mi], pa_hi, 40);
                wmma::load_matrix_sync(al[mi], pa_lo, 40);
            }
#pragma unroll
            for (int ni = 0; ni < 4; ni++) {
                wmma::fragment<wmma::matrix_b, 16, 16, 16, __nv_bfloat16, wmma::row_major> bh, bl;
                const __nv_bfloat16* pb_hi = reinterpret_cast<const __nv_bfloat16*>(stage + W_HI)
                                           + (ks * 16) * 136 + wn * 64 + ni * 16;
                const __nv_bfloat16* pb_lo = reinterpret_cast<const __nv_bfloat16*>(stage + W_LO)
                                           + (ks * 16) * 136 + wn * 64 + ni * 16;
                wmma::load_matrix_sync(bh, pb_hi, 136);
                wmma::load_matrix_sync(bl, pb_lo, 136);
#pragma unroll
                for (int mi = 0; mi < 2; mi++) {
                    wmma::mma_sync(acc[mi][ni], ah[mi], bh, acc[mi][ni]);
                    wmma::mma_sync(acc[mi][ni], ah[mi], bl, acc[mi][ni]);
                    wmma::mma_sync(acc[mi][ni], al[mi], bh, acc[mi][ni]);
                }
            }
        }
    }

    // ---------------- Epilogue: bias + relu + residual ---------------------
    __syncthreads();
    float* sc = reinterpret_cast<float*>(stage) + wid * (16 * 68);
    const int col0 = wn * 64;
    const int rl   = lane >> 1;
    const int half = lane & 1;
#pragma unroll
    for (int mi = 0; mi < 2; mi++) {
#pragma unroll
        for (int ni = 0; ni < 4; ni++)
            wmma::store_matrix_sync(sc + ni * 16, acc[mi][ni], 68, wmma::mem_row_major);
        __syncwarp();
        int grow = row0 + wm * 32 + mi * 16 + rl;
        if (grow < N_NODES) {
#pragma unroll
            for (int j = 0; j < 8; j++) {
                int c = half * 32 + j * 4;
                float4 v  = *reinterpret_cast<const float4*>(sc + rl * 68 + c);
                float4 b4 = *reinterpret_cast<const float4*>(bias + col0 + c);
                v.x += b4.x; v.y += b4.y; v.z += b4.z; v.w += b4.w;
                v.x = fmaxf(v.x, 0.f); v.y = fmaxf(v.y, 0.f);
                v.z = fmaxf(v.z, 0.f); v.w = fmaxf(v.w, 0.f);
                float4 rr = *reinterpret_cast<const float4*>(hin + (size_t)grow * DIM + col0 + c);
                v.x += rr.x; v.y += rr.y; v.z += rr.z; v.w += rr.w;
                *reinterpret_cast<float4*>(out + (size_t)grow * DIM + col0 + c) = v;
            }
        }
        __syncwarp();
    }
}

// ---------------------------------------------------------------------------
// CSR construction: histogram -> hierarchical scan -> fill
// ---------------------------------------------------------------------------
__global__ void zero_deg_kernel() {
    int i = blockIdx.x * blockDim.x + threadIdx.x;
    if (i < N_NODES) g_deg[i] = 0;
}

__global__ void hist_kernel(const int* __restrict__ dst) {
    int e = blockIdx.x * blockDim.x + threadIdx.x;
    if (e < N_EDGES) atomicAdd(&g_deg[dst[e]], 1);
}

__global__ void block_reduce_kernel() {
    __shared__ int sh[256];
    int tid = threadIdx.x;
    int i = blockIdx.x * 256 + tid;
    int v = (i < N_NODES) ? g_deg[i] : 0;
    sh[tid] = v;
    __syncthreads();
#pragma unroll
    for (int s = 128; s > 0; s >>= 1) {
        if (tid < s) sh[tid] += sh[tid + s];
        __syncthreads();
    }
    if (tid == 0) g_bsum[blockIdx.x] = sh[0];
}

__global__ void scan_bsum_kernel() {
    __shared__ int sh[256];
    int tid = threadIdx.x;
    int v = (tid < NBLK_NODE) ? g_bsum[tid] : 0;
    sh[tid] = v;
    __syncthreads();
#pragma unroll
    for (int off = 1; off < 256; off <<= 1) {
        int t = (tid >= off) ? sh[tid - off] : 0;
        __syncthreads();
        sh[tid] += t;
        __syncthreads();
    }
    if (tid < NBLK_NODE) g_bbase[tid] = sh[tid] - v;
    if (tid == 0) g_off[N_NODES] = N_EDGES;
}

__global__ void scan_write_kernel() {
    __shared__ int sh[256];
    int tid = threadIdx.x;
    int i = blockIdx.x * 256 + tid;
    int v = (i < N_NODES) ? g_deg[i] : 0;
    sh[tid] = v;
    __syncthreads();
#pragma unroll
    for (int off = 1; off < 256; off <<= 1) {
        int t = (tid >= off) ? sh[tid - off] : 0;
        __syncthreads();
        sh[tid] += t;
        __syncthreads();
    }
    if (i < N_NODES) {
        int o = g_bbase[blockIdx.x] + sh[tid] - v;
        g_off[i] = o;
        g_cur[i] = o;
    }
}

__global__ void fill_kernel(const int* __restrict__ src, const int* __restrict__ dst) {
    int e = blockIdx.x * blockDim.x + threadIdx.x;
    if (e < N_EDGES) {
        int d = dst[e];
        int pos = atomicAdd(&g_cur[d], 1);
        g_srcs[pos] = src[e];
    }
}

// ---------------------------------------------------------------------------
// Launch
// ---------------------------------------------------------------------------
extern "C" void kernel_launch(void* const* d_in, const int* in_sizes, int n_in,
                              void* d_out, int out_size)
{
    const float* x       = (const float*)d_in[0];
    const int*   ei      = (const int*)  d_in[1];
    const float* in_fc_w = (const float*)d_in[2];
    const float* in_fc_b = (const float*)d_in[3];
    const float* w_rel   = (const float*)d_in[4];
    const float* b_rel   = (const float*)d_in[5];
    const float* w_root  = (const float*)d_in[6];
    float* out = (float*)d_out;

    const int* src = ei;
    const int* dst = ei + N_EDGES;

    float* hA; cudaGetSymbolAddress((void**)&hA, g_hA);
    float* hB; cudaGetSymbolAddress((void**)&hB, g_hB);

    static int smem_set = 0;
    if (!smem_set) {
        cudaFuncSetAttribute(fused_layer_kernel,
                             cudaFuncAttributeMaxDynamicSharedMemorySize, FUSED_SMEM);
        smem_set = 1;
    }

    const int GEMM_BLOCKS = (N_NODES + 127) / 128;       // 391
    const int EDGE_BLOCKS = (N_EDGES + 255) / 256;       // 3125

    // CSR build
    zero_deg_kernel<<<NBLK_NODE, 256>>>();
    hist_kernel<<<EDGE_BLOCKS, 256>>>(dst);
    block_reduce_kernel<<<NBLK_NODE, 256>>>();
    scan_bsum_kernel<<<1, 256>>>();
    scan_write_kernel<<<NBLK_NODE, 256>>>();
    fill_kernel<<<EDGE_BLOCKS, 256>>>(src, dst);

    // in_fc: hA = x @ in_fc_w + b
    gemm_infc_kernel<<<GEMM_BLOCKS, 256>>>(x, in_fc_w, in_fc_b, hA);

    // 3 fused GraphConv layers (gather + GEMM + epilogue), ping-pong h
    fused_layer_kernel<<<GEMM_BLOCKS, 256, FUSED_SMEM>>>(
        hA, w_rel, w_root, b_rel, hB);
    fused_layer_kernel<<<GEMM_BLOCKS, 256, FUSED_SMEM>>>(
        hB, w_rel + DIM * DIM, w_root + DIM * DIM, b_rel + DIM, hA);
    fused_layer_kernel<<<GEMM_BLOCKS, 256, FUSED_SMEM>>>(
        hA, w_rel + 2 * DIM * DIM, w_root + 2 * DIM * DIM, b_rel + 2 * DIM, out);
}